// round 11
// baseline (speedup 1.0000x reference)
#include <cuda_runtime.h>
#include <cuda_bf16.h>
#include <math.h>

// EMA with SD, chunked parallel scan (round 10).
// x (T=8192, D=128); h_a0, h_sd0, alpha (N=32, D=128).
// out: (T, 2N, D) fp32, then hN_a (N,D), hN_sd (N,D).
//
// pass1: CS=128 chunks of LS=64; FOUR independent 16-step sub-streams per
//        thread (4x MLP), merged exactly via quadratic-map composition:
//          P' = W*P0 + P1
//          A' = W*(A0 + (1-W)*P0^2 - 2*P0*P1) + A1      (W = b^len(first))
// combine: folds 128 summaries per lane with W=b^64:
//          hv' = W*hv + W(1-W)*ha^2 - 2W*P*ha + A ; ha' = W*ha + P
//          writes replay entry state at every chunk (CR = CS = 128).
// pass2: CR=128 chunks of LR=64, float4 lanes (STG.128), 64-thread blocks,
//        4096 resident warps (proven residency) — store-issue-cost model
//        says 1.05M STG.128 ~ 24us issue, leaving DRAM-write floor ~45us.

#define TT 8192
#define DD 128
#define NN 32
#define CS 128
#define LS 64
#define QS 16           // sub-stream length (LS/4)
#define CR 128
#define LR 64
#define LANES (NN * DD)

__device__ float g_P  [CS * LANES];
__device__ float g_A  [CS * LANES];
__device__ float g_ha0[CR * LANES];
__device__ float g_hv0[CR * LANES];

__device__ __forceinline__ float sqrt_fast(float v) {
    float r;
    asm("sqrt.approx.f32 %0, %1;" : "=f"(r) : "f"(v));
    return r;
}

// ---------------------------------------------------------------- pass 1
__global__ __launch_bounds__(64) void ema_pass1(
    const float* __restrict__ x,
    const float* __restrict__ alpha)
{
    const int c  = blockIdx.x;           // 0..CS-1
    const int n  = blockIdx.y;           // 0..NN-1
    const int t  = threadIdx.x;          // 0..63
    const int idx = n * DD + 2 * t;

    const float2 al = *reinterpret_cast<const float2*>(alpha + idx);
    const float a0 = al.x, a1 = al.y;
    const float b0 = 1.0f - a0, b1 = 1.0f - a1;

    const float2* xp = reinterpret_cast<const float2*>(x + (size_t)c * LS * DD + 2 * t);

    // Four independent 16-step sub-streams (time offsets 0,16,32,48)
    float gP0a = 0.f, gP0b = 0.f, AA0a = 0.f, AA0b = 0.f;
    float gP1a = 0.f, gP1b = 0.f, AA1a = 0.f, AA1b = 0.f;
    float gP2a = 0.f, gP2b = 0.f, AA2a = 0.f, AA2b = 0.f;
    float gP3a = 0.f, gP3b = 0.f, AA3a = 0.f, AA3b = 0.f;

#pragma unroll 4
    for (int i = 0; i < QS; ++i) {
        const float2 x0 = xp[(size_t)(i          ) * (DD / 2)];
        const float2 x1 = xp[(size_t)(i + QS     ) * (DD / 2)];
        const float2 x2 = xp[(size_t)(i + 2 * QS ) * (DD / 2)];
        const float2 x3 = xp[(size_t)(i + 3 * QS ) * (DD / 2)];
        float u;
        u = x0.x - gP0a; gP0a = fmaf(a0, u, gP0a); AA0a = b0 * fmaf(a0, u * u, AA0a);
        u = x0.y - gP0b; gP0b = fmaf(a1, u, gP0b); AA0b = b1 * fmaf(a1, u * u, AA0b);
        u = x1.x - gP1a; gP1a = fmaf(a0, u, gP1a); AA1a = b0 * fmaf(a0, u * u, AA1a);
        u = x1.y - gP1b; gP1b = fmaf(a1, u, gP1b); AA1b = b1 * fmaf(a1, u * u, AA1b);
        u = x2.x - gP2a; gP2a = fmaf(a0, u, gP2a); AA2a = b0 * fmaf(a0, u * u, AA2a);
        u = x2.y - gP2b; gP2b = fmaf(a1, u, gP2b); AA2b = b1 * fmaf(a1, u * u, AA2b);
        u = x3.x - gP3a; gP3a = fmaf(a0, u, gP3a); AA3a = b0 * fmaf(a0, u * u, AA3a);
        u = x3.y - gP3b; gP3b = fmaf(a1, u, gP3b); AA3b = b1 * fmaf(a1, u * u, AA3b);
    }

    // W16 = b^16, per lane
    float W16a, W16b;
    {
        float p = b0 * b0; p *= p; p *= p; W16a = p * p;
    }
    {
        float p = b1 * b1; p *= p; p *= p; W16b = p * p;
    }

    // merge (first,second) with weight W of the first chunk's length:
    //   P' = W*P0 + P1 ;  A' = W*(A0 + (1-W)P0^2 - 2*P0*P1) + A1
    // lane a: merge streams 0+1 and 2+3 at W16, then merge results at W32.
    float Pa01 = fmaf(W16a, gP0a, gP1a);
    float Aa01 = fmaf(W16a, AA0a + fmaf((1.f - W16a) * gP0a, gP0a, -2.f * gP0a * gP1a), AA1a);
    float Pa23 = fmaf(W16a, gP2a, gP3a);
    float Aa23 = fmaf(W16a, AA2a + fmaf((1.f - W16a) * gP2a, gP2a, -2.f * gP2a * gP3a), AA3a);
    const float W32a = W16a * W16a;
    const float Pa = fmaf(W32a, Pa01, Pa23);
    const float Aa = fmaf(W32a, Aa01 + fmaf((1.f - W32a) * Pa01, Pa01, -2.f * Pa01 * Pa23), Aa23);

    float Pb01 = fmaf(W16b, gP0b, gP1b);
    float Ab01 = fmaf(W16b, AA0b + fmaf((1.f - W16b) * gP0b, gP0b, -2.f * gP0b * gP1b), AA1b);
    float Pb23 = fmaf(W16b, gP2b, gP3b);
    float Ab23 = fmaf(W16b, AA2b + fmaf((1.f - W16b) * gP2b, gP2b, -2.f * gP2b * gP3b), AA3b);
    const float W32b = W16b * W16b;
    const float Pb = fmaf(W32b, Pb01, Pb23);
    const float Ab = fmaf(W32b, Ab01 + fmaf((1.f - W32b) * Pb01, Pb01, -2.f * Pb01 * Pb23), Ab23);

    const int s = c * LANES + idx;
    *reinterpret_cast<float2*>(g_P + s) = make_float2(Pa, Pb);
    *reinterpret_cast<float2*>(g_A + s) = make_float2(Aa, Ab);
}

// ---------------------------------------------------------------- combine
__global__ __launch_bounds__(DD) void ema_combine(
    const float* __restrict__ h_a0,
    const float* __restrict__ h_sd0,
    const float* __restrict__ alpha,
    float* __restrict__ out,
    int write_tail)
{
    const int n = blockIdx.x;
    const int d = threadIdx.x;
    const int idx = n * DD + d;

    const float a = alpha[idx];
    const float b = 1.0f - a;
    float W;   // b^64
    {
        float p = b * b; p *= p; p *= p; p *= p; p *= p; W = p * p;
    }
    const float Cq  = W * (1.0f - W);
    const float m2W = -2.0f * W;

    float ha = h_a0[idx];
    const float sd = h_sd0[idx];
    float hv = sd * sd;

#pragma unroll 8
    for (int c = 0; c < CS; ++c) {
        const int e = c * LANES + idx;
        g_ha0[e] = ha;
        g_hv0[e] = hv;
        const float P = g_P[e];
        const float A = g_A[e];
        const float hv_new = fmaf(W, hv, fmaf(Cq, ha * ha, fmaf(m2W * P, ha, A)));
        hv = fmaxf(hv_new, 0.0f);
        ha = fmaf(W, ha, P);
    }

    if (write_tail) {
        const size_t base = (size_t)TT * 2 * NN * DD;
        out[base + idx]         = ha;          // hN_a
        out[base + LANES + idx] = sqrtf(hv);   // hN_sd
    }
}

// ---------------------------------------------------------------- pass 2
// CR=128 x LR=64, float4 lanes. Block = 64 thr = 2 warps; each warp covers
// one n-row (32 lanes x 4 d). Grid (CR, NN/2) = 2048 blocks = 4096 warps.
__global__ __launch_bounds__(64) void ema_pass2(
    const float* __restrict__ x,
    const float* __restrict__ alpha,
    float* __restrict__ out)
{
    const int c = blockIdx.x;                          // 0..CR-1
    const int n = blockIdx.y * 2 + (threadIdx.x >> 5); // 0..NN-1
    const int l = threadIdx.x & 31;
    const int d = 4 * l;
    const int idx = n * DD + d;

    const float4 al = *reinterpret_cast<const float4*>(alpha + idx);
    const float a0 = al.x, a1 = al.y, a2 = al.z, a3 = al.w;
    const float b0 = 1.0f - a0, b1 = 1.0f - a1, b2 = 1.0f - a2, b3 = 1.0f - a3;

    const int s = c * LANES + idx;
    const float4 hav = *reinterpret_cast<const float4*>(g_ha0 + s);
    const float4 hvv = *reinterpret_cast<const float4*>(g_hv0 + s);
    float ha0 = hav.x, ha1 = hav.y, ha2 = hav.z, ha3 = hav.w;
    float hv0 = hvv.x, hv1 = hvv.y, hv2 = hvv.z, hv3 = hvv.w;

    const float4* xp = reinterpret_cast<const float4*>(x + (size_t)c * LR * DD + d);
    float* obase = out + (size_t)c * LR * (2 * NN * DD) + idx;

#pragma unroll 8
    for (int i = 0; i < LR; ++i) {
        const float4 xv = xp[(size_t)i * (DD / 4)];
        const float u0 = xv.x - ha0, u1 = xv.y - ha1;
        const float u2 = xv.z - ha2, u3 = xv.w - ha3;
        ha0 = fmaf(a0, u0, ha0);
        ha1 = fmaf(a1, u1, ha1);
        ha2 = fmaf(a2, u2, ha2);
        ha3 = fmaf(a3, u3, ha3);
        hv0 = b0 * fmaf(a0, u0 * u0, hv0);
        hv1 = b1 * fmaf(a1, u1 * u1, hv1);
        hv2 = b2 * fmaf(a2, u2 * u2, hv2);
        hv3 = b3 * fmaf(a3, u3 * u3, hv3);
        float* op = obase + (size_t)i * (2 * NN * DD);
        __stcs(reinterpret_cast<float4*>(op),
               make_float4(ha0, ha1, ha2, ha3));
        __stcs(reinterpret_cast<float4*>(op + NN * DD),
               make_float4(sqrt_fast(hv0), sqrt_fast(hv1),
                           sqrt_fast(hv2), sqrt_fast(hv3)));
    }
}

extern "C" void kernel_launch(void* const* d_in, const int* in_sizes, int n_in,
                              void* d_out, int out_size)
{
    const float* x     = (const float*)d_in[0];
    const float* h_a0  = (const float*)d_in[1];
    const float* h_sd0 = (const float*)d_in[2];
    const float* alpha = (const float*)d_in[3];
    float* out = (float*)d_out;

    const int main_elems = TT * 2 * NN * DD;
    const int write_tail = (out_size > main_elems) ? 1 : 0;

    dim3 grid1(CS, NN);
    ema_pass1<<<grid1, 64>>>(x, alpha);
    ema_combine<<<NN, DD>>>(h_a0, h_sd0, alpha, out, write_tail);
    dim3 grid2(CR, NN / 2);
    ema_pass2<<<grid2, 64>>>(x, alpha, out);
}

// round 12
// speedup vs baseline: 1.8153x; 1.8153x over previous
#include <cuda_runtime.h>
#include <cuda_bf16.h>
#include <math.h>

// EMA with SD, chunked parallel scan (round 12).
// x (T=8192, D=128); h_a0, h_sd0, alpha (N=32, D=128).
// out: (T, 2N, D) fp32, then hN_a (N,D), hN_sd (N,D).
//
// Two kernels only:
// pass1 (r9's proven 12.9us): CS=128 chunks of LS=64, dual independent
//   32-step sub-streams per thread, merged exactly via quadratic-map
//   composition:  P' = W*P0 + P1,
//                 A' = W*(A0 + (1-W)P0^2 - 2*P0*P1) + A1   (W = b^32)
// pass2 (r4's proven 62us store shape: CR=64 x LR=128, float2 lanes,
//   64-thr blocks, 4096 warps, __stcs streaming stores, sqrt.approx):
//   each block (c,n) first folds summaries 0..2c-1 (W=b^64 per fold) to
//   reconstruct its exact chunk-entry state — redundant across blocks but
//   parallel, ordered by the kernel boundary (no flags/spins) — then runs
//   the exact per-step replay. c=CR-1 blocks emit hN_a / hN_sd.

#define TT 8192
#define DD 128
#define NN 32
#define CS 128
#define LS 64
#define HS 32           // pass1 sub-stream length
#define CR 64
#define LR 128
#define LANES (NN * DD)

__device__ float g_P[CS * LANES];
__device__ float g_A[CS * LANES];

__device__ __forceinline__ float sqrt_fast(float v) {
    float r;
    asm("sqrt.approx.f32 %0, %1;" : "=f"(r) : "f"(v));
    return r;
}

// ---------------------------------------------------------------- pass 1
// (byte-identical to round-9's measured best)
__global__ __launch_bounds__(64) void ema_pass1(
    const float* __restrict__ x,
    const float* __restrict__ alpha)
{
    const int c  = blockIdx.x;           // 0..CS-1
    const int n  = blockIdx.y;           // 0..NN-1
    const int t  = threadIdx.x;          // 0..63
    const int idx = n * DD + 2 * t;

    const float2 al = *reinterpret_cast<const float2*>(alpha + idx);
    const float a0 = al.x, a1 = al.y;
    const float b0 = 1.0f - a0, b1 = 1.0f - a1;

    const float2* xp0 = reinterpret_cast<const float2*>(x + (size_t)c * LS * DD + 2 * t);
    const float2* xp1 = xp0 + (size_t)HS * (DD / 2);

    float g0a = 0.f, g0b = 0.f, A0a = 0.f, A0b = 0.f;   // stream 0
    float g1a = 0.f, g1b = 0.f, A1a = 0.f, A1b = 0.f;   // stream 1

#pragma unroll 8
    for (int i = 0; i < HS; ++i) {
        const float2 x0 = xp0[(size_t)i * (DD / 2)];
        const float2 x1 = xp1[(size_t)i * (DD / 2)];
        const float u0a = x0.x - g0a, u0b = x0.y - g0b;
        const float u1a = x1.x - g1a, u1b = x1.y - g1b;
        g0a = fmaf(a0, u0a, g0a);
        g0b = fmaf(a1, u0b, g0b);
        g1a = fmaf(a0, u1a, g1a);
        g1b = fmaf(a1, u1b, g1b);
        A0a = b0 * fmaf(a0, u0a * u0a, A0a);
        A0b = b1 * fmaf(a1, u0b * u0b, A0b);
        A1a = b0 * fmaf(a0, u1a * u1a, A1a);
        A1b = b1 * fmaf(a1, u1b * u1b, A1b);
    }

    float W0, W1;   // b^32 per lane
    {
        float p = b0 * b0; p *= p; p *= p; p *= p; W0 = p * p;
    }
    {
        float p = b1 * b1; p *= p; p *= p; p *= p; W1 = p * p;
    }
    const float Pm0 = fmaf(W0, g0a, g1a);
    const float Pm1 = fmaf(W1, g0b, g1b);
    const float Am0 = fmaf(W0, A0a, A1a)
                    + W0 * fmaf((1.0f - W0) * g0a, g0a, -2.0f * g0a * g1a);
    const float Am1 = fmaf(W1, A0b, A1b)
                    + W1 * fmaf((1.0f - W1) * g0b, g0b, -2.0f * g0b * g1b);

    const int s = c * LANES + idx;
    *reinterpret_cast<float2*>(g_P + s) = make_float2(Pm0, Pm1);
    *reinterpret_cast<float2*>(g_A + s) = make_float2(Am0, Am1);
}

// ---------------------------------------------------------------- pass 2
// Fold own prefix (no combine kernel), then exact replay (r4 shape).
__global__ __launch_bounds__(64) void ema_pass2(
    const float* __restrict__ x,
    const float* __restrict__ h_a0,
    const float* __restrict__ h_sd0,
    const float* __restrict__ alpha,
    float* __restrict__ out,
    int write_tail)
{
    const int c  = blockIdx.x;           // 0..CR-1
    const int n  = blockIdx.y;           // 0..NN-1
    const int d2 = threadIdx.x;          // 0..63
    const int idx = n * DD + 2 * d2;

    const float2 al = *reinterpret_cast<const float2*>(alpha + idx);
    const float a0 = al.x, a1 = al.y;
    const float b0 = 1.0f - a0, b1 = 1.0f - a1;

    // per-lane fold constants: W = b^64
    float W0, W1;
    {
        float p = b0 * b0; p *= p; p *= p; p *= p; p *= p; W0 = p * p;
    }
    {
        float p = b1 * b1; p *= p; p *= p; p *= p; p *= p; W1 = p * p;
    }
    const float Cq0 = W0 * (1.0f - W0), Cq1 = W1 * (1.0f - W1);
    const float m2W0 = -2.0f * W0,      m2W1 = -2.0f * W1;

    // entry state: fold summaries 0 .. 2c-1 (LS=64 granularity)
    const float2 hav = *reinterpret_cast<const float2*>(h_a0 + idx);
    const float2 sdv = *reinterpret_cast<const float2*>(h_sd0 + idx);
    float ha0 = hav.x, ha1 = hav.y;
    float hv0 = sdv.x * sdv.x, hv1 = sdv.y * sdv.y;

    const int nfold = 2 * c;
#pragma unroll 4
    for (int cc = 0; cc < nfold; ++cc) {
        const int s = cc * LANES + idx;
        const float2 P  = *reinterpret_cast<const float2*>(g_P + s);
        const float2 Aa = *reinterpret_cast<const float2*>(g_A + s);
        float hvn;
        hvn = fmaf(W0, hv0, fmaf(Cq0, ha0 * ha0, fmaf(m2W0 * P.x, ha0, Aa.x)));
        hv0 = fmaxf(hvn, 0.f);
        ha0 = fmaf(W0, ha0, P.x);
        hvn = fmaf(W1, hv1, fmaf(Cq1, ha1 * ha1, fmaf(m2W1 * P.y, ha1, Aa.y)));
        hv1 = fmaxf(hvn, 0.f);
        ha1 = fmaf(W1, ha1, P.y);
    }

    // exact replay with streaming stores (r4's proven shape)
    const float2* xp = reinterpret_cast<const float2*>(x + (size_t)c * LR * DD + 2 * d2);
    float2* obase = reinterpret_cast<float2*>(out + (size_t)c * LR * 2 * NN * DD + n * DD + 2 * d2);

#pragma unroll 8
    for (int i = 0; i < LR; ++i) {
        const float2 xv = xp[(size_t)i * (DD / 2)];
        const float u0 = xv.x - ha0;
        const float u1 = xv.y - ha1;
        ha0 = fmaf(a0, u0, ha0);
        ha1 = fmaf(a1, u1, ha1);
        hv0 = b0 * fmaf(a0, u0 * u0, hv0);
        hv1 = b1 * fmaf(a1, u1 * u1, hv1);
        float2* op = obase + (size_t)i * (NN * DD);      // i * 4096 float2
        __stcs(op, make_float2(ha0, ha1));
        __stcs(op + (NN * DD / 2), make_float2(sqrt_fast(hv0), sqrt_fast(hv1)));
    }

    // tail: final states from the last chunk's replay-exit state
    if (write_tail && c == CR - 1) {
        const size_t base = (size_t)TT * 2 * NN * DD;
        *reinterpret_cast<float2*>(out + base + idx) = make_float2(ha0, ha1);
        *reinterpret_cast<float2*>(out + base + LANES + idx) =
            make_float2(sqrt_fast(hv0), sqrt_fast(hv1));
    }
}

extern "C" void kernel_launch(void* const* d_in, const int* in_sizes, int n_in,
                              void* d_out, int out_size)
{
    const float* x     = (const float*)d_in[0];
    const float* h_a0  = (const float*)d_in[1];
    const float* h_sd0 = (const float*)d_in[2];
    const float* alpha = (const float*)d_in[3];
    float* out = (float*)d_out;

    const int main_elems = TT * 2 * NN * DD;
    const int write_tail = (out_size > main_elems) ? 1 : 0;

    dim3 grid1(CS, NN);
    ema_pass1<<<grid1, 64>>>(x, alpha);
    dim3 grid2(CR, NN);
    ema_pass2<<<grid2, 64>>>(x, h_a0, h_sd0, alpha, out, write_tail);
}